// round 6
// baseline (speedup 1.0000x reference)
#include <cuda_runtime.h>

// Lorenz96 RK4, batch x 40 fp32.
// Two rows packed per thread via fma.rn.f32x2 (rows r, r+3 of a 6-row warp tile).
// 10 threads per row-pair, 4 packed elements each; halos via 64-bit shuffles.
// In-place y update (3 state arrays) + forced 6 CTAs/SM for occupancy.

#define N_STATE 40
#define TPB 256
#define WARPS_PER_BLOCK (TPB / 32)
#define ROWS_PER_WARP 6

typedef unsigned long long ull;

__device__ __forceinline__ ull pack2(float lo, float hi) {
    ull r;
    asm("mov.b64 %0, {%1, %2};" : "=l"(r) : "f"(lo), "f"(hi));
    return r;
}
__device__ __forceinline__ void unpack2(ull v, float& lo, float& hi) {
    asm("mov.b64 {%0, %1}, %2;" : "=f"(lo), "=f"(hi) : "l"(v));
}
__device__ __forceinline__ ull fma2(ull a, ull b, ull c) {
    ull d;
    asm("fma.rn.f32x2 %0, %1, %2, %3;" : "=l"(d) : "l"(a), "l"(b), "l"(c));
    return d;
}

#define NEG1_2 0xBF800000BF800000ULL   // (-1, -1)
#define F_2    0x4100000041000000ULL   // ( 8,  8)  FORCE

// k = (y_{i+1} - y_{i-2}) * y_{i-1} + (F - y_i), on packed row pairs.
// Reads y[0..3] (+3 halos), writes k[0..3].
__device__ __forceinline__ void eval_k(const ull* __restrict__ y,
                                       ull* __restrict__ k,
                                       unsigned mask, int left, int right) {
    const ull hL2 = __shfl_sync(mask, y[2], left);   // i-2 at e=0
    const ull hL3 = __shfl_sync(mask, y[3], left);   // i-1 at e=0, i-2 at e=1
    const ull hR0 = __shfl_sync(mask, y[0], right);  // i+1 at e=3

    k[0] = fma2(fma2(hL2,  NEG1_2, y[1]), hL3,  fma2(y[0], NEG1_2, F_2));
    k[1] = fma2(fma2(hL3,  NEG1_2, y[2]), y[0], fma2(y[1], NEG1_2, F_2));
    k[2] = fma2(fma2(y[0], NEG1_2, y[3]), y[1], fma2(y[2], NEG1_2, F_2));
    k[3] = fma2(fma2(y[1], NEG1_2, hR0),  y[2], fma2(y[3], NEG1_2, F_2));
}

__global__ __launch_bounds__(TPB, 6)
void lorenz96_rk4_kernel(const float4* __restrict__ x0,
                         const float* __restrict__ dt_ptr,
                         float4* __restrict__ out,
                         int batch) {
    const int lane = threadIdx.x & 31;
    if (lane >= 30) return;                 // lanes 30,31 idle (in no shfl mask)

    const int g = (lane >= 20) ? 2 : (lane >= 10 ? 1 : 0);  // row-pair group
    const int t = lane - g * 10;                            // element chunk 0..9

    const int warp = blockIdx.x * WARPS_PER_BLOCK + (threadIdx.x >> 5);
    const int rowA = warp * ROWS_PER_WARP + g;   // pair = rows (rowA, rowA+3)
    if (rowA >= batch) return;                   // uniform within 10-lane group
    const bool bOK = (rowA + 3 < batch);

    const unsigned mask = 0x3FFu << (g * 10);
    const int base = g * 10;
    const int left  = (t == 0) ? base + 9 : lane - 1;
    const int right = (t == 9) ? base     : lane + 1;

    const float dt = __ldg(dt_ptr);
    const ull dt2  = pack2(dt, dt);
    const ull hdt2 = pack2(0.5f * dt, 0.5f * dt);
    const float sdt = dt * (1.0f / 6.0f);
    const ull sdt2 = pack2(sdt, sdt);

    // Coalesced loads; rowB is rowA+3 -> +30 float4.
    const float4* __restrict__ pin = x0 + (rowA * 10 + t);
    const float4 va = pin[0];
    const float4 vb = bOK ? pin[30] : va;

    ull x[4] = { pack2(va.x, vb.x), pack2(va.y, vb.y),
                 pack2(va.z, vb.z), pack2(va.w, vb.w) };

    ull acc[4], y[4], k[4];

    // k1 (from x): acc = k; y = x + dt/2 * k
    eval_k(x, k, mask, left, right);
#pragma unroll
    for (int e = 0; e < 4; e++) {
        acc[e] = k[e];
        y[e] = fma2(k[e], hdt2, x[e]);
    }
    // k2: acc += 2k; y = x + dt/2 * k   (in place; k computed before overwrite)
    eval_k(y, k, mask, left, right);
#pragma unroll
    for (int e = 0; e < 4; e++) {
        acc[e] = fma2(k[e], pack2(2.0f, 2.0f), acc[e]);
        y[e] = fma2(k[e], hdt2, x[e]);
    }
    // k3: acc += 2k; y = x + dt * k
    eval_k(y, k, mask, left, right);
#pragma unroll
    for (int e = 0; e < 4; e++) {
        acc[e] = fma2(k[e], pack2(2.0f, 2.0f), acc[e]);
        y[e] = fma2(k[e], dt2, x[e]);
    }
    // k4: acc += k
    eval_k(y, k, mask, left, right);
#pragma unroll
    for (int e = 0; e < 4; e++)
        acc[e] = fma2(k[e], pack2(1.0f, 1.0f), acc[e]);

    // out = x + dt/6 * acc
    float4 oa, ob;
    unpack2(fma2(acc[0], sdt2, x[0]), oa.x, ob.x);
    unpack2(fma2(acc[1], sdt2, x[1]), oa.y, ob.y);
    unpack2(fma2(acc[2], sdt2, x[2]), oa.z, ob.z);
    unpack2(fma2(acc[3], sdt2, x[3]), oa.w, ob.w);

    float4* __restrict__ pout = out + (rowA * 10 + t);
    pout[0] = oa;
    if (bOK) pout[30] = ob;
}

extern "C" void kernel_launch(void* const* d_in, const int* in_sizes, int n_in,
                              void* d_out, int out_size) {
    const float4* x0 = (const float4*)d_in[0];
    // d_in[1] is t (unused, autonomous system)
    const float* dt = (const float*)d_in[2];
    float4* out = (float4*)d_out;

    const int batch = in_sizes[0] / N_STATE;
    const int rows_per_block = WARPS_PER_BLOCK * ROWS_PER_WARP;  // 48
    const int blocks = (batch + rows_per_block - 1) / rows_per_block;
    lorenz96_rk4_kernel<<<blocks, TPB>>>(x0, dt, out, batch);
}

// round 7
// speedup vs baseline: 1.2944x; 1.2944x over previous
#include <cuda_runtime.h>

// Lorenz96 RK4, batch x 40 fp32.
// R5 compute body (fma.rn.f32x2, rows r/r+3 packed, 10 threads per row-pair,
// halos via 64-bit shuffles) + software-pipelined grid chunks:
// each warp-group processes ITERS consecutive 6-row windows, prefetching the
// next window's loads before computing the current one.

#define N_STATE 40
#define TPB 256
#define WARPS_PER_BLOCK (TPB / 32)
#define ROWS_PER_WARP 6
#define ITERS 4

typedef unsigned long long ull;

__device__ __forceinline__ ull pack2(float lo, float hi) {
    ull r;
    asm("mov.b64 %0, {%1, %2};" : "=l"(r) : "f"(lo), "f"(hi));
    return r;
}
__device__ __forceinline__ void unpack2(ull v, float& lo, float& hi) {
    asm("mov.b64 {%0, %1}, %2;" : "=f"(lo), "=f"(hi) : "l"(v));
}
__device__ __forceinline__ ull fma2(ull a, ull b, ull c) {
    ull d;
    asm("fma.rn.f32x2 %0, %1, %2, %3;" : "=l"(d) : "l"(a), "l"(b), "l"(c));
    return d;
}

#define NEG1_2 0xBF800000BF800000ULL   // (-1, -1)
#define ONE_2  0x3F8000003F800000ULL   // ( 1,  1)
#define TWO_2  0x4000000040000000ULL   // ( 2,  2)
#define F_2    0x4100000041000000ULL   // ( 8,  8)  FORCE

template <bool FIRST, bool HAS_NEXT>
__device__ __forceinline__ void stage(const ull* __restrict__ y,
                                      ull* __restrict__ acc,
                                      const ull* __restrict__ x,
                                      ull* __restrict__ yn,
                                      ull W2, ull C2,
                                      unsigned mask, int left, int right) {
    const ull hL2 = __shfl_sync(mask, y[2], left);   // i-2 at e=0
    const ull hL3 = __shfl_sync(mask, y[3], left);   // i-1 at e=0, i-2 at e=1
    const ull hR0 = __shfl_sync(mask, y[0], right);  // i+1 at e=3

    const ull yp1[4] = { y[1], y[2], y[3], hR0 };
    const ull ym1[4] = { hL3,  y[0], y[1], y[2] };
    const ull ym2[4] = { hL2,  hL3,  y[0], y[1] };

#pragma unroll
    for (int e = 0; e < 4; e++) {
        const ull d = fma2(ym2[e], NEG1_2, yp1[e]);   // y_{i+1} - y_{i-2}
        const ull t = fma2(y[e],   NEG1_2, F_2);      // F - y_i
        const ull k = fma2(d, ym1[e], t);
        if (FIRST)
            acc[e] = k;
        else
            acc[e] = fma2(k, W2, acc[e]);
        if (HAS_NEXT)
            yn[e] = fma2(k, C2, x[e]);
    }
}

__global__ __launch_bounds__(TPB, 4)
void lorenz96_rk4_kernel(const float4* __restrict__ x0,
                         const float* __restrict__ dt_ptr,
                         float4* __restrict__ out,
                         int batch) {
    const int lane = threadIdx.x & 31;
    if (lane >= 30) return;                 // lanes 30,31 idle (in no shfl mask)

    const int g = (lane >= 20) ? 2 : (lane >= 10 ? 1 : 0);  // row-pair group
    const int t = lane - g * 10;                            // element chunk

    const int warp = blockIdx.x * WARPS_PER_BLOCK + (threadIdx.x >> 5);
    const long long row0 = (long long)warp * (ROWS_PER_WARP * ITERS) + g;

    const unsigned mask = 0x3FFu << (g * 10);
    const int base = g * 10;
    const int left  = (t == 0) ? base + 9 : lane - 1;
    const int right = (t == 9) ? base     : lane + 1;

    const float dt = __ldg(dt_ptr);
    const ull dt2  = pack2(dt, dt);
    const ull hdt2 = pack2(0.5f * dt, 0.5f * dt);
    const float sdt = dt * (1.0f / 6.0f);
    const ull sdt2 = pack2(sdt, sdt);

    const float4* __restrict__ pin  = x0  + (row0 * 10 + t);
    float4*       __restrict__ pout = out + (row0 * 10 + t);

    long long r = row0;
    bool aOK = (r < batch);
    bool bOK = (r + 3 < batch);
    float4 va, vb;
    if (aOK) va = pin[0];
    if (bOK) vb = pin[30];

#pragma unroll
    for (int i = 0; i < ITERS; i++) {
        // ---- Prefetch next window (rows +6) before computing current ----
        float4 na, nb;
        bool naOK = false, nbOK = false;
        if (i + 1 < ITERS) {
            const long long rn = r + ROWS_PER_WARP;
            naOK = (rn < batch);
            nbOK = (rn + 3 < batch);
            if (naOK) na = pin[60];
            if (nbOK) nb = pin[90];
        }

        // ---- Compute current window (guarded; uniform within 10-lane group) ----
        if (aOK) {
            ull x[4] = { pack2(va.x, vb.x), pack2(va.y, vb.y),
                         pack2(va.z, vb.z), pack2(va.w, vb.w) };
            ull acc[4], ya[4], yb[4];

            stage<true,  true >(x,  acc, x, ya, ONE_2, hdt2, mask, left, right);
            stage<false, true >(ya, acc, x, yb, TWO_2, hdt2, mask, left, right);
            stage<false, true >(yb, acc, x, ya, TWO_2, dt2,  mask, left, right);
            stage<false, false>(ya, acc, x, yb, ONE_2, dt2,  mask, left, right);

            float4 oa, ob;
            unpack2(fma2(acc[0], sdt2, x[0]), oa.x, ob.x);
            unpack2(fma2(acc[1], sdt2, x[1]), oa.y, ob.y);
            unpack2(fma2(acc[2], sdt2, x[2]), oa.z, ob.z);
            unpack2(fma2(acc[3], sdt2, x[3]), oa.w, ob.w);

            pout[0] = oa;
            if (bOK) pout[30] = ob;
        }

        va = na; vb = nb;
        aOK = naOK; bOK = nbOK;
        r += ROWS_PER_WARP;
        pin += 60; pout += 60;
    }
}

extern "C" void kernel_launch(void* const* d_in, const int* in_sizes, int n_in,
                              void* d_out, int out_size) {
    const float4* x0 = (const float4*)d_in[0];
    // d_in[1] is t (unused, autonomous system)
    const float* dt = (const float*)d_in[2];
    float4* out = (float4*)d_out;

    const int batch = in_sizes[0] / N_STATE;
    const int rows_per_block = WARPS_PER_BLOCK * ROWS_PER_WARP * ITERS;  // 192
    const int blocks = (batch + rows_per_block - 1) / rows_per_block;
    lorenz96_rk4_kernel<<<blocks, TPB>>>(x0, dt, out, batch);
}